// round 11
// baseline (speedup 1.0000x reference)
#include <cuda_runtime.h>
#include <cuda_fp16.h>
#include <cstdint>

// NearestEmbed: x (64,64,32,32) f32, emb (64,512) f32
// out f32 = [ quantized 4194304 | argmin 65536 (as float) ]
//
// R11: two kernels.
//  1) vq_main: HMMA coarse + in-warp exact fp32 rescue (R6/R10 loop, unchanged
//     arithmetic). 256 thr/CTA, launch_bounds(256,3) -> 24 warps/SM. smem =
//     frags(64KB)+norms only; emits indices only.
//  2) vq_gather: emb in smem, gathers winning codes to out_q. Store-bound.

#define MTHREADS 256           // 8 warps, warp owns 16 rows
#define TILE_M 128
#define MGRID 512              // 512 tiles of 128 rows
#define EMB_D 64
#define EMB_K 512
#define HW 1024
#define MARGIN 0.04f

// main-kernel smem (bytes)
#define SM_FRAGS 0                       // u32 frags[64 nt][4 ks][32 lane][2] = 64KB
#define SM_NORMS 65536                   // f32 [512] = 2KB
#define SM_WSM   (SM_NORMS + 2048)       // i32 [8 warps][16]
#define SM_XS    (SM_WSM + 512)          // f32 [8 warps][64] = 2KB
#define SM_TOTAL (SM_XS + 2048)

#define GTHREADS 512
#define GGRID 128                        // 512 rows per CTA
#define GSMEM (EMB_D * EMB_K * 4)        // 128KB

__device__ __forceinline__ uint32_t packh2(float a, float b) {
    __half2 h = __floats2half2_rn(a, b);
    return *reinterpret_cast<uint32_t*>(&h);
}

__device__ __forceinline__ void hmma16816(float& c0, float& c1, float& c2, float& c3,
                                          uint32_t a0, uint32_t a1, uint32_t a2, uint32_t a3,
                                          uint32_t b0, uint32_t b1) {
    asm volatile("mma.sync.aligned.m16n8k16.row.col.f32.f16.f16.f32 "
                 "{%0,%1,%2,%3}, {%4,%5,%6,%7}, {%8,%9}, {%0,%1,%2,%3};"
                 : "+f"(c0), "+f"(c1), "+f"(c2), "+f"(c3)
                 : "r"(a0), "r"(a1), "r"(a2), "r"(a3), "r"(b0), "r"(b1));
}

__global__ __launch_bounds__(MTHREADS, 3)
void vq_main(const float* __restrict__ x,
             const float* __restrict__ emb,
             float* __restrict__ out_idx)
{
    extern __shared__ char smem[];
    uint32_t* frags = reinterpret_cast<uint32_t*>(smem + SM_FRAGS);
    float*    norms = reinterpret_cast<float*>(smem + SM_NORMS);

    const int tid  = threadIdx.x;
    const int warp = tid >> 5;
    const int lane = tid & 31;
    const int gidq = lane & 3;
    const int grp  = lane >> 2;

    int*   wsm = reinterpret_cast<int*>(smem + SM_WSM) + warp * 16;
    float* xs  = reinterpret_cast<float*>(smem + SM_XS) + warp * 64;

    // ---- Prologue: norms + B fragments from global emb ----
    for (int k = tid; k < EMB_K; k += MTHREADS) {
        float s = 0.f;
        #pragma unroll 8
        for (int d = 0; d < EMB_D; d++) {
            float v = __ldg(emb + d * EMB_K + k);
            s = fmaf(v, v, s);
        }
        norms[k] = s;
    }
    // frags[((nt*4+ks)*32 + lane)*2 + j]; n = nt*8+lane/4, d0 = ks*16+2*(lane%4)+8*j
    for (int f = tid; f < 64 * 4 * 32 * 2; f += MTHREADS) {
        int j  = f & 1;
        int ln = (f >> 1) & 31;
        int ks = (f >> 6) & 3;
        int nt = f >> 8;
        int n  = nt * 8 + (ln >> 2);
        int d0 = ks * 16 + 2 * (ln & 3) + 8 * j;
        frags[f] = packh2(__ldg(emb + d0 * EMB_K + n), __ldg(emb + (d0 + 1) * EMB_K + n));
    }
    __syncthreads();   // warps fully independent afterwards

    const int row_base = blockIdx.x * TILE_M;
    const int b = row_base >> 10;
    const int hw_base = row_base & (HW - 1);
    const float* xb = x + (size_t)b * (EMB_D * HW) + hw_base;   // x(row,d)=xb[d*HW+row]
    const int wrow = warp * 16;

    // ---- A fragments: this warp's 16 rows ----
    const float* xw = xb + wrow;
    uint32_t A[4][4];
    {
        const int q2 = gidq * 2;
        #pragma unroll
        for (int ks = 0; ks < 4; ks++) {
            int d = ks * 16 + q2;
            A[ks][0] = packh2(xw[d * HW + grp],           xw[(d + 1) * HW + grp]);
            A[ks][1] = packh2(xw[d * HW + grp + 8],       xw[(d + 1) * HW + grp + 8]);
            A[ks][2] = packh2(xw[(d + 8) * HW + grp],     xw[(d + 9) * HW + grp]);
            A[ks][3] = packh2(xw[(d + 8) * HW + grp + 8], xw[(d + 9) * HW + grp + 8]);
        }
    }

    // ---- coarse scan over 64 n-tiles (R6 loop, unchanged) ----
    float b1a = __int_as_float(0x7f800000), b2a = b1a; int k1a = 0;  // row grp
    float b1b = b1a, b2b = b1a; int k1b = 0;                          // row grp+8

    const uint2* fr2 = reinterpret_cast<const uint2*>(frags);
    #pragma unroll 4
    for (int nt = 0; nt < 64; nt++) {
        float c0 = 0.f, c1 = 0.f, c2 = 0.f, c3 = 0.f;
        #pragma unroll
        for (int ks = 0; ks < 4; ks++) {
            uint2 bb = fr2[(nt * 4 + ks) * 32 + lane];
            hmma16816(c0, c1, c2, c3, A[ks][0], A[ks][1], A[ks][2], A[ks][3], bb.x, bb.y);
        }
        const int n0 = nt * 8 + gidq * 2;
        float2 nr = *reinterpret_cast<const float2*>(norms + n0);
        float s0 = fmaf(-2.f, c0, nr.x);
        float s1 = fmaf(-2.f, c1, nr.y);
        float s2 = fmaf(-2.f, c2, nr.x);
        float s3 = fmaf(-2.f, c3, nr.y);
        if (s0 < b1a) { b2a = b1a; b1a = s0; k1a = n0; } else b2a = fminf(b2a, s0);
        if (s1 < b1a) { b2a = b1a; b1a = s1; k1a = n0 + 1; } else b2a = fminf(b2a, s1);
        if (s2 < b1b) { b2b = b1b; b1b = s2; k1b = n0; } else b2b = fminf(b2b, s2);
        if (s3 < b1b) { b2b = b1b; b1b = s3; k1b = n0 + 1; } else b2b = fminf(b2b, s3);
    }

    // ---- merge across the 4 lanes of each row-group ----
    #pragma unroll
    for (int off = 1; off <= 2; off <<= 1) {
        float ob1 = __shfl_xor_sync(0xffffffffu, b1a, off);
        int   ok1 = __shfl_xor_sync(0xffffffffu, k1a, off);
        float ob2 = __shfl_xor_sync(0xffffffffu, b2a, off);
        float nb2 = fminf(fmaxf(b1a, ob1), fminf(b2a, ob2));
        bool take = (ob1 < b1a) || (ob1 == b1a && ok1 < k1a);
        b1a = take ? ob1 : b1a; k1a = take ? ok1 : k1a; b2a = nb2;

        float pb1 = __shfl_xor_sync(0xffffffffu, b1b, off);
        int   pk1 = __shfl_xor_sync(0xffffffffu, k1b, off);
        float pb2 = __shfl_xor_sync(0xffffffffu, b2b, off);
        float qb2 = fminf(fmaxf(b1b, pb1), fminf(b2b, pb2));
        bool tk2 = (pb1 < b1b) || (pb1 == b1b && pk1 < k1b);
        b1b = tk2 ? pb1 : b1b; k1b = tk2 ? pk1 : k1b; b2b = qb2;
    }

    // ---- record winners, mark ambiguous rows (in-warp) ----
    bool ownA = (gidq == 0);
    bool ambA = ownA && (b2a - b1a <= MARGIN);
    bool ambB = ownA && (b2b - b1b <= MARGIN);
    if (ownA) {
        wsm[grp]     = k1a;
        wsm[grp + 8] = k1b;
    }
    uint32_t mA = __ballot_sync(0xffffffffu, ambA);
    uint32_t mB = __ballot_sync(0xffffffffu, ambB);
    __syncwarp();

    uint32_t amb = 0;
    #pragma unroll
    for (int g = 0; g < 8; g++) {
        amb |= ((mA >> (4 * g)) & 1u) << g;
        amb |= ((mB >> (4 * g)) & 1u) << (g + 8);
    }

    // ---- in-warp exact fp32 rescue (rare; emb via L2, capped unrolls) ----
    while (amb) {
        int r = __ffs(amb) - 1;
        amb &= amb - 1;
        const float* xg = xb + wrow + r;
        xs[lane]      = xg[(size_t)lane * HW];
        xs[lane + 32] = xg[(size_t)(lane + 32) * HW];
        __syncwarp();
        float best = __int_as_float(0x7f800000);
        int bk = 0;
        #pragma unroll 1
        for (int j = 0; j < 16; j++) {
            int k = lane + 32 * j;
            float acc = 0.f;
            #pragma unroll 8
            for (int d = 0; d < EMB_D; d++)
                acc = fmaf(xs[d], __ldg(emb + d * EMB_K + k), acc);
            float sc = fmaf(-2.f, acc, norms[k]);
            if (sc < best) { best = sc; bk = k; }
        }
        #pragma unroll
        for (int off = 16; off >= 1; off >>= 1) {
            float os = __shfl_xor_sync(0xffffffffu, best, off);
            int   ok = __shfl_xor_sync(0xffffffffu, bk, off);
            bool take = (os < best) || (os == best && ok < bk);
            best = take ? os : best;
            bk = take ? ok : bk;
        }
        if (lane == 0) wsm[r] = bk;
        __syncwarp();
    }
    __syncwarp();

    if (lane < 16) out_idx[row_base + wrow + lane] = (float)wsm[lane];
}

// ---- gather kernel: out_q[b][d][hw] = emb[d][k(n)], store-bound ----
__global__ __launch_bounds__(GTHREADS, 1)
void vq_gather(const float* __restrict__ emb,
               const float* __restrict__ out_idx,
               float* __restrict__ out_q)
{
    extern __shared__ float emb_s[];   // [64][512]
    const int tid = threadIdx.x;
    #pragma unroll
    for (int i = 0; i < EMB_D * EMB_K / GTHREADS; i++)
        emb_s[i * GTHREADS + tid] = emb[i * GTHREADS + tid];
    __syncthreads();

    const int n = blockIdx.x * GTHREADS + tid;       // this thread's row
    const int b = n >> 10;
    const int hw = n & (HW - 1);
    const int k = (int)out_idx[n];

    float* oq = out_q + (size_t)b * (EMB_D * HW) + hw;
    #pragma unroll
    for (int d = 0; d < EMB_D; d++)
        oq[(size_t)d * HW] = emb_s[d * EMB_K + k];   // stores coalesced across warp
}

extern "C" void kernel_launch(void* const* d_in, const int* in_sizes, int n_in,
                              void* d_out, int out_size)
{
    const float* x   = (const float*)d_in[0];   // 4194304 f32
    const float* emb = (const float*)d_in[1];   // 32768 f32
    float* out_q = (float*)d_out;
    float* out_i = (float*)d_out + (size_t)4194304;

    cudaFuncSetAttribute(vq_main,
                         cudaFuncAttributeMaxDynamicSharedMemorySize, SM_TOTAL);
    cudaFuncSetAttribute(vq_gather,
                         cudaFuncAttributeMaxDynamicSharedMemorySize, GSMEM);

    vq_main<<<MGRID, MTHREADS, SM_TOTAL>>>(x, emb, out_i);
    vq_gather<<<GGRID, GTHREADS, GSMEM>>>(emb, out_i, out_q);
}

// round 12
// speedup vs baseline: 2.3997x; 2.3997x over previous
#include <cuda_runtime.h>
#include <cuda_fp16.h>
#include <cstdint>

// NearestEmbed: x (64,64,32,32) f32, emb (64,512) f32
// out f32 = [ quantized 4194304 | argmin 65536 (as float) ]
//
// R12: R6 loop with TWO M=16 A-tiles per warp (32 rows): each B-fragment LDS
// feeds 2 independent HMMA chains -> 2x independent work per warp against the
// same latencies. 512 thr (16 warps), 1 CTA/SM, grid 128 x 512 rows, no
// launch_bounds reg cap (spills proven fatal in R7/R11).

#define THREADS 512            // 16 warps, warp owns 32 rows
#define TILE_M 512             // rows per CTA
#define GRID 128
#define EMB_D 64
#define EMB_K 512
#define HW 1024
#define MARGIN 0.04f

// smem layout (bytes)
#define SM_FRAGS 0                       // u32 frags[64 nt][4 ks][32 lane][2] = 64KB
#define SM_EMB   65536                   // f32 emb_s[64][512] = 128KB
#define SM_NORMS (SM_EMB + 131072)       // f32 [512] = 2KB
#define SM_WSM   (SM_NORMS + 2048)       // i32 [16 warps][32 rows] = 2KB
#define SM_XS    (SM_WSM + 2048)         // f32 [16 warps][64] = 4KB
#define SM_TOTAL (SM_XS + 4096)

__device__ __forceinline__ uint32_t packh2(float a, float b) {
    __half2 h = __floats2half2_rn(a, b);
    return *reinterpret_cast<uint32_t*>(&h);
}

__device__ __forceinline__ void hmma16816(float& c0, float& c1, float& c2, float& c3,
                                          uint32_t a0, uint32_t a1, uint32_t a2, uint32_t a3,
                                          uint32_t b0, uint32_t b1) {
    asm volatile("mma.sync.aligned.m16n8k16.row.col.f32.f16.f16.f32 "
                 "{%0,%1,%2,%3}, {%4,%5,%6,%7}, {%8,%9}, {%0,%1,%2,%3};"
                 : "+f"(c0), "+f"(c1), "+f"(c2), "+f"(c3)
                 : "r"(a0), "r"(a1), "r"(a2), "r"(a3), "r"(b0), "r"(b1));
}

// top-2 update for a pair of adjacent-code scores
__device__ __forceinline__ void top2_pair(float s0, float s1, int n0,
                                          float& b1, float& b2, int& k1) {
    if (s0 < b1) { b2 = b1; b1 = s0; k1 = n0; } else b2 = fminf(b2, s0);
    if (s1 < b1) { b2 = b1; b1 = s1; k1 = n0 + 1; } else b2 = fminf(b2, s1);
}

// lane-merge of top-2 state across xor offsets 1,2
__device__ __forceinline__ void lane_merge(float& b1, float& b2, int& k1) {
    #pragma unroll
    for (int off = 1; off <= 2; off <<= 1) {
        float ob1 = __shfl_xor_sync(0xffffffffu, b1, off);
        int   ok1 = __shfl_xor_sync(0xffffffffu, k1, off);
        float ob2 = __shfl_xor_sync(0xffffffffu, b2, off);
        float nb2 = fminf(fmaxf(b1, ob1), fminf(b2, ob2));
        bool take = (ob1 < b1) || (ob1 == b1 && ok1 < k1);
        b1 = take ? ob1 : b1; k1 = take ? ok1 : k1; b2 = nb2;
    }
}

__global__ __launch_bounds__(THREADS, 1)
void vq_hmma_kernel(const float* __restrict__ x,
                    const float* __restrict__ emb,
                    float* __restrict__ out_q,
                    float* __restrict__ out_idx)
{
    extern __shared__ char smem[];
    uint32_t* frags = reinterpret_cast<uint32_t*>(smem + SM_FRAGS);
    float*    emb_s = reinterpret_cast<float*>(smem + SM_EMB);
    float*    norms = reinterpret_cast<float*>(smem + SM_NORMS);

    const int tid  = threadIdx.x;
    const int warp = tid >> 5;
    const int lane = tid & 31;
    const int gidq = lane & 3;
    const int grp  = lane >> 2;

    int*   wsm = reinterpret_cast<int*>(smem + SM_WSM) + warp * 32;
    float* xs  = reinterpret_cast<float*>(smem + SM_XS) + warp * 64;

    // ---- Prologue (once per CTA) ----
    for (int i = tid; i < EMB_D * EMB_K; i += THREADS) emb_s[i] = emb[i];
    __syncthreads();

    for (int k = tid; k < EMB_K; k += THREADS) {
        float s = 0.f;
        #pragma unroll
        for (int d = 0; d < EMB_D; d++) {
            float v = emb_s[d * EMB_K + k];
            s = fmaf(v, v, s);
        }
        norms[k] = s;
    }
    // B fragments: frags[((nt*4+ks)*32 + lane)*2 + j]
    for (int f = tid; f < 64 * 4 * 32 * 2; f += THREADS) {
        int j  = f & 1;
        int ln = (f >> 1) & 31;
        int ks = (f >> 6) & 3;
        int nt = f >> 8;
        int n  = nt * 8 + (ln >> 2);
        int d0 = ks * 16 + 2 * (ln & 3) + 8 * j;
        frags[f] = packh2(emb_s[d0 * EMB_K + n], emb_s[(d0 + 1) * EMB_K + n]);
    }
    __syncthreads();   // warps fully independent afterwards

    const int row_base = blockIdx.x * TILE_M;
    const int b = row_base >> 10;
    const int hw_base = row_base & (HW - 1);
    const float* xb = x + (size_t)b * (EMB_D * HW) + hw_base;   // x(row,d)=xb[d*HW+row]
    const int wrow = warp * 32;

    // ---- A fragments: two 16-row tiles ----
    const float* xw0 = xb + wrow;
    const float* xw1 = xb + wrow + 16;
    uint32_t A0[4][4], A1[4][4];
    {
        const int q2 = gidq * 2;
        #pragma unroll
        for (int ks = 0; ks < 4; ks++) {
            int d = ks * 16 + q2;
            A0[ks][0] = packh2(xw0[d * HW + grp],           xw0[(d + 1) * HW + grp]);
            A0[ks][1] = packh2(xw0[d * HW + grp + 8],       xw0[(d + 1) * HW + grp + 8]);
            A0[ks][2] = packh2(xw0[(d + 8) * HW + grp],     xw0[(d + 9) * HW + grp]);
            A0[ks][3] = packh2(xw0[(d + 8) * HW + grp + 8], xw0[(d + 9) * HW + grp + 8]);
            A1[ks][0] = packh2(xw1[d * HW + grp],           xw1[(d + 1) * HW + grp]);
            A1[ks][1] = packh2(xw1[d * HW + grp + 8],       xw1[(d + 1) * HW + grp + 8]);
            A1[ks][2] = packh2(xw1[(d + 8) * HW + grp],     xw1[(d + 9) * HW + grp]);
            A1[ks][3] = packh2(xw1[(d + 8) * HW + grp + 8], xw1[(d + 9) * HW + grp + 8]);
        }
    }

    // ---- coarse scan over 64 n-tiles, 4 row-groups of top-2 state ----
    const float INF = __int_as_float(0x7f800000);
    float b1a = INF, b2a = INF, b1b = INF, b2b = INF;   // tile0 rows grp, grp+8
    float b1c = INF, b2c = INF, b1d = INF, b2d = INF;   // tile1 rows grp+16, grp+24
    int k1a = 0, k1b = 0, k1c = 0, k1d = 0;

    const uint2* fr2 = reinterpret_cast<const uint2*>(frags);
    #pragma unroll 2
    for (int nt = 0; nt < 64; nt++) {
        float c0 = 0.f, c1 = 0.f, c2 = 0.f, c3 = 0.f;   // tile0
        float e0 = 0.f, e1 = 0.f, e2 = 0.f, e3 = 0.f;   // tile1
        #pragma unroll
        for (int ks = 0; ks < 4; ks++) {
            uint2 bb = fr2[(nt * 4 + ks) * 32 + lane];
            hmma16816(c0, c1, c2, c3, A0[ks][0], A0[ks][1], A0[ks][2], A0[ks][3], bb.x, bb.y);
            hmma16816(e0, e1, e2, e3, A1[ks][0], A1[ks][1], A1[ks][2], A1[ks][3], bb.x, bb.y);
        }
        const int n0 = nt * 8 + gidq * 2;
        float2 nr = *reinterpret_cast<const float2*>(norms + n0);
        top2_pair(fmaf(-2.f, c0, nr.x), fmaf(-2.f, c1, nr.y), n0, b1a, b2a, k1a);
        top2_pair(fmaf(-2.f, c2, nr.x), fmaf(-2.f, c3, nr.y), n0, b1b, b2b, k1b);
        top2_pair(fmaf(-2.f, e0, nr.x), fmaf(-2.f, e1, nr.y), n0, b1c, b2c, k1c);
        top2_pair(fmaf(-2.f, e2, nr.x), fmaf(-2.f, e3, nr.y), n0, b1d, b2d, k1d);
    }

    lane_merge(b1a, b2a, k1a);
    lane_merge(b1b, b2b, k1b);
    lane_merge(b1c, b2c, k1c);
    lane_merge(b1d, b2d, k1d);

    // ---- record winners, build 32-bit ambiguous mask (in-warp) ----
    bool own = (gidq == 0);
    if (own) {
        wsm[grp]      = k1a;
        wsm[grp + 8]  = k1b;
        wsm[grp + 16] = k1c;
        wsm[grp + 24] = k1d;
    }
    uint32_t mA = __ballot_sync(0xffffffffu, own && (b2a - b1a <= MARGIN));
    uint32_t mB = __ballot_sync(0xffffffffu, own && (b2b - b1b <= MARGIN));
    uint32_t mC = __ballot_sync(0xffffffffu, own && (b2c - b1c <= MARGIN));
    uint32_t mD = __ballot_sync(0xffffffffu, own && (b2d - b1d <= MARGIN));
    __syncwarp();

    uint32_t amb = 0;
    #pragma unroll
    for (int g = 0; g < 8; g++) {
        amb |= ((mA >> (4 * g)) & 1u) << g;
        amb |= ((mB >> (4 * g)) & 1u) << (g + 8);
        amb |= ((mC >> (4 * g)) & 1u) << (g + 16);
        amb |= ((mD >> (4 * g)) & 1u) << (g + 24);
    }

    // ---- in-warp exact fp32 rescue for ambiguous rows (rare) ----
    while (amb) {
        int r = __ffs(amb) - 1;
        amb &= amb - 1;
        const float* xg = xb + wrow + r;
        xs[lane]      = xg[(size_t)lane * HW];
        xs[lane + 32] = xg[(size_t)(lane + 32) * HW];
        __syncwarp();
        float best = __int_as_float(0x7f800000);
        int bk = 0;
        #pragma unroll 1
        for (int j = 0; j < 16; j++) {
            int k = lane + 32 * j;
            float acc = 0.f;
            #pragma unroll 8
            for (int d = 0; d < EMB_D; d++)
                acc = fmaf(xs[d], emb_s[d * EMB_K + k], acc);
            float sc = fmaf(-2.f, acc, norms[k]);
            if (sc < best) { best = sc; bk = k; }
        }
        #pragma unroll
        for (int off = 16; off >= 1; off >>= 1) {
            float os = __shfl_xor_sync(0xffffffffu, best, off);
            int   ok = __shfl_xor_sync(0xffffffffu, bk, off);
            bool take = (os < best) || (os == best && ok < bk);
            best = take ? os : best;
            bk = take ? ok : bk;
        }
        if (lane == 0) wsm[r] = bk;
        __syncwarp();
    }
    __syncwarp();

    // ---- in-warp outputs: this warp's 32 rows ----
    float* oq = out_q + (size_t)b * (EMB_D * HW) + hw_base + wrow;
    #pragma unroll 8
    for (int i = lane; i < 32 * EMB_D; i += 32) {
        int r = i & 31;
        int d = i >> 5;
        oq[(size_t)d * HW + r] = emb_s[d * EMB_K + wsm[r]];
    }
    out_idx[row_base + wrow + lane] = (float)wsm[lane];
}

extern "C" void kernel_launch(void* const* d_in, const int* in_sizes, int n_in,
                              void* d_out, int out_size)
{
    const float* x   = (const float*)d_in[0];   // 4194304 f32
    const float* emb = (const float*)d_in[1];   // 32768 f32
    float* out_q = (float*)d_out;
    float* out_i = (float*)d_out + (size_t)4194304;

    cudaFuncSetAttribute(vq_hmma_kernel,
                         cudaFuncAttributeMaxDynamicSharedMemorySize, SM_TOTAL);
    vq_hmma_kernel<<<GRID, THREADS, SM_TOTAL>>>(x, emb, out_q, out_i);
}